// round 2
// baseline (speedup 1.0000x reference)
#include <cuda_runtime.h>
#include <cuda_bf16.h>

// ---------------- problem constants ----------------
#define Bb 128
#define T 512
#define H 1024
#define O 256
#define TS 511              // scan steps = T-1
#define M_TOTAL (Bb*T)      // 65536
#define CHUNK 32
#define NC 16               // 16*32 = 512 >= 511

#define ALPHA_F   0.9048374180359595f
#define OMA_F     0.09516258196404048f
#define ALPHA32_F 0.040762204f          // alpha^32

// ---------------- scratch (static device arrays; no allocation) ----------------
__device__ float          g_h2[(size_t)M_TOTAL * O];   // 64 MB
__device__ __nv_bfloat16  g_wbf[H * O];                // 512 KB
__device__ float          g_L[NC * Bb * O];            // chunk local sums
__device__ float          g_S[NC * Bb * O];            // mem_start per chunk
__device__ float          g_part[NC * Bb * O];         // per-chunk softmax partials

// ---------------- kernel 0: W fp32 -> bf16 ----------------
__global__ void k_convw(const float* __restrict__ w) {
    int i = blockIdx.x * blockDim.x + threadIdx.x;
    if (i < H * O) g_wbf[i] = __float2bfloat16(w[i]);
}

// ---------------- kernel 1: GEMM h2 = x @ W (bf16 mma.sync, fp32 accum) ----------------
#define BM 128
#define BN 256
#define BK 64
#define NKT (H / BK)   // 16

__device__ __forceinline__ unsigned a_swz(int m, int kb) {
    unsigned off = (unsigned)(m * 128 + kb);        // 128B rows
    return off ^ ((off >> 3) & 0x70);               // bits[6:4] ^= m%8
}
__device__ __forceinline__ unsigned b_swz(int k, int nb) {
    unsigned off = (unsigned)(k * 512 + nb);        // 512B rows
    return off ^ ((off >> 5) & 0x70);               // bits[6:4] ^= k%8
}

__global__ __launch_bounds__(512, 1) void k_gemm(const float* __restrict__ x) {
    extern __shared__ __align__(16) unsigned char smem_raw[];
    const unsigned smem_base = (unsigned)__cvta_generic_to_shared(smem_raw);
    const unsigned asb[2] = { smem_base,          smem_base + 16384u };
    const unsigned bsb[2] = { smem_base + 32768u, smem_base + 65536u };

    const int tid  = threadIdx.x;
    const int lane = tid & 31;
    const int wid  = tid >> 5;
    const int wm   = wid >> 2;        // 0..3  (rows of 32)
    const int wn   = wid & 3;         // 0..3  (cols of 64)
    const int row0 = blockIdx.x * BM;

    float acc[2][8][4];
#pragma unroll
    for (int i = 0; i < 2; i++)
#pragma unroll
        for (int j = 0; j < 8; j++)
#pragma unroll
            for (int k = 0; k < 4; k++) acc[i][j][k] = 0.f;

    int a_m[4], a_ks[4], b_k[4], b_c[4];
#pragma unroll
    for (int i = 0; i < 4; i++) {
        int idx = tid + 512 * i;
        a_m[i] = idx >> 4;  a_ks[i] = idx & 15;    // 16 float4 per 64-float row
        b_k[i] = idx >> 5;  b_c[i]  = idx & 31;    // 32 16B-chunks per 256-bf16 row
    }

    // ---- prologue: tile 0 ----
#pragma unroll
    for (int i = 0; i < 4; i++) {
        unsigned dst = bsb[0] + b_swz(b_k[i], b_c[i] * 16);
        const __nv_bfloat16* src = g_wbf + (size_t)(b_k[i]) * O + b_c[i] * 8;
        asm volatile("cp.async.cg.shared.global [%0], [%1], 16;\n" :: "r"(dst), "l"(src));
    }
    asm volatile("cp.async.commit_group;\n");

    float4 av[4];
#pragma unroll
    for (int i = 0; i < 4; i++)
        av[i] = *reinterpret_cast<const float4*>(
            x + (size_t)(row0 + a_m[i]) * H + a_ks[i] * 4);
#pragma unroll
    for (int i = 0; i < 4; i++) {
        unsigned dst = asb[0] + a_swz(a_m[i], a_ks[i] * 8);
        __nv_bfloat162 lo = __floats2bfloat162_rn(av[i].x, av[i].y);
        __nv_bfloat162 hi = __floats2bfloat162_rn(av[i].z, av[i].w);
        unsigned ulo = *reinterpret_cast<unsigned*>(&lo);
        unsigned uhi = *reinterpret_cast<unsigned*>(&hi);
        asm volatile("st.shared.v2.b32 [%0], {%1,%2};\n" :: "r"(dst), "r"(ulo), "r"(uhi));
    }
    asm volatile("cp.async.wait_group 0;\n");
    __syncthreads();

    for (int kt = 0; kt < NKT; ++kt) {
        const int cur = kt & 1, nxt = cur ^ 1;

        if (kt + 1 < NKT) {
#pragma unroll
            for (int i = 0; i < 4; i++) {
                unsigned dst = bsb[nxt] + b_swz(b_k[i], b_c[i] * 16);
                const __nv_bfloat16* src =
                    g_wbf + (size_t)((kt + 1) * BK + b_k[i]) * O + b_c[i] * 8;
                asm volatile("cp.async.cg.shared.global [%0], [%1], 16;\n" :: "r"(dst), "l"(src));
            }
            asm volatile("cp.async.commit_group;\n");
#pragma unroll
            for (int i = 0; i < 4; i++)
                av[i] = *reinterpret_cast<const float4*>(
                    x + (size_t)(row0 + a_m[i]) * H + (kt + 1) * BK + a_ks[i] * 4);
        }

        // ---- compute current tile ----
#pragma unroll
        for (int ks = 0; ks < 4; ++ks) {
            const int k0 = ks * 16;
            unsigned af[2][4];
#pragma unroll
            for (int mt = 0; mt < 2; mt++) {
                int q = lane >> 3, r = lane & 7;
                int mrow = wm * 32 + mt * 16 + ((q & 1) << 3) + r;
                int kk = k0 + ((q >> 1) << 3);
                unsigned addr = asb[cur] + a_swz(mrow, kk * 2);
                asm volatile("ldmatrix.sync.aligned.m8n8.x4.shared.b16 {%0,%1,%2,%3}, [%4];\n"
                             : "=r"(af[mt][0]), "=r"(af[mt][1]), "=r"(af[mt][2]), "=r"(af[mt][3])
                             : "r"(addr));
            }
            unsigned bf[8][2];
#pragma unroll
            for (int g = 0; g < 4; g++) {
                int q = lane >> 3, r = lane & 7;
                int kk = k0 + ((q & 1) << 3) + r;
                int nn = wn * 64 + g * 16 + ((q >> 1) << 3);
                unsigned addr = bsb[cur] + b_swz(kk, nn * 2);
                asm volatile("ldmatrix.sync.aligned.m8n8.x4.trans.shared.b16 {%0,%1,%2,%3}, [%4];\n"
                             : "=r"(bf[2 * g][0]), "=r"(bf[2 * g][1]),
                               "=r"(bf[2 * g + 1][0]), "=r"(bf[2 * g + 1][1])
                             : "r"(addr));
            }
#pragma unroll
            for (int mt = 0; mt < 2; mt++)
#pragma unroll
                for (int nt = 0; nt < 8; nt++)
                    asm volatile(
                        "mma.sync.aligned.m16n8k16.row.col.f32.bf16.bf16.f32 "
                        "{%0,%1,%2,%3}, {%4,%5,%6,%7}, {%8,%9}, {%0,%1,%2,%3};\n"
                        : "+f"(acc[mt][nt][0]), "+f"(acc[mt][nt][1]),
                          "+f"(acc[mt][nt][2]), "+f"(acc[mt][nt][3])
                        : "r"(af[mt][0]), "r"(af[mt][1]), "r"(af[mt][2]), "r"(af[mt][3]),
                          "r"(bf[nt][0]), "r"(bf[nt][1]));
        }

        if (kt + 1 < NKT) {
#pragma unroll
            for (int i = 0; i < 4; i++) {
                unsigned dst = asb[nxt] + a_swz(a_m[i], a_ks[i] * 8);
                __nv_bfloat162 lo = __floats2bfloat162_rn(av[i].x, av[i].y);
                __nv_bfloat162 hi = __floats2bfloat162_rn(av[i].z, av[i].w);
                unsigned ulo = *reinterpret_cast<unsigned*>(&lo);
                unsigned uhi = *reinterpret_cast<unsigned*>(&hi);
                asm volatile("st.shared.v2.b32 [%0], {%1,%2};\n" :: "r"(dst), "r"(ulo), "r"(uhi));
            }
            asm volatile("cp.async.wait_group 0;\n");
        }
        __syncthreads();
    }

    // ---- epilogue: write h2 ----
    const int g = lane >> 2, cc = lane & 3;
#pragma unroll
    for (int mt = 0; mt < 2; mt++) {
#pragma unroll
        for (int nt = 0; nt < 8; nt++) {
            int rm = row0 + wm * 32 + mt * 16 + g;
            int col = wn * 64 + nt * 8 + 2 * cc;
            float2 v0 = make_float2(acc[mt][nt][0], acc[mt][nt][1]);
            float2 v1 = make_float2(acc[mt][nt][2], acc[mt][nt][3]);
            *reinterpret_cast<float2*>(g_h2 + (size_t)rm * O + col) = v0;
            *reinterpret_cast<float2*>(g_h2 + (size_t)(rm + 8) * O + col) = v1;
        }
    }
}

// ---------------- kernel 2: per-chunk local scaled sums L_c ----------------
// L_c = sum_{i=0}^{31} alpha^{31-i} (1-alpha) h_{t0+i}  == recurrence from 0
__global__ void k_carry() {
    int w = (blockIdx.x * blockDim.x + threadIdx.x) >> 5;   // 0..1919
    int lane = threadIdx.x & 31;
    int b = w & 127;
    int c = w >> 7;                                          // 0..14
    float L[8] = {0, 0, 0, 0, 0, 0, 0, 0};
    const float4* base =
        (const float4*)(g_h2 + ((size_t)b * T + c * CHUNK) * O);
#pragma unroll 4
    for (int i = 0; i < CHUNK; ++i) {
        float4 h0 = base[i * 64 + lane];
        float4 h1 = base[i * 64 + 32 + lane];
        L[0] = fmaf(ALPHA_F, L[0], OMA_F * h0.x);
        L[1] = fmaf(ALPHA_F, L[1], OMA_F * h0.y);
        L[2] = fmaf(ALPHA_F, L[2], OMA_F * h0.z);
        L[3] = fmaf(ALPHA_F, L[3], OMA_F * h0.w);
        L[4] = fmaf(ALPHA_F, L[4], OMA_F * h1.x);
        L[5] = fmaf(ALPHA_F, L[5], OMA_F * h1.y);
        L[6] = fmaf(ALPHA_F, L[6], OMA_F * h1.z);
        L[7] = fmaf(ALPHA_F, L[7], OMA_F * h1.w);
    }
    float4* dst = (float4*)(g_L + ((size_t)c * Bb + b) * O);
    dst[lane]      = make_float4(L[0], L[1], L[2], L[3]);
    dst[32 + lane] = make_float4(L[4], L[5], L[6], L[7]);
}

// ---------------- kernel 3: sequential scan of chunk carries ----------------
__global__ void k_scanS() {
    int i = blockIdx.x * blockDim.x + threadIdx.x;   // 0..32767 == b*256+o
    float S = 0.f;
    g_S[i] = 0.f;                                    // chunk 0 starts at mem=0
#pragma unroll
    for (int c = 0; c < NC - 1; ++c) {
        S = ALPHA32_F * S + g_L[c * (Bb * O) + i];
        g_S[(c + 1) * (Bb * O) + i] = S;
    }
}

// ---------------- kernel 4: per-chunk softmax scan (exact) ----------------
__global__ void k_soft() {
    int w = (blockIdx.x * blockDim.x + threadIdx.x) >> 5;   // 0..2047
    int lane = threadIdx.x & 31;
    int b = w & 127;
    int c = w >> 7;                                          // 0..15
    int t0 = c * CHUNK;
    int niter = min(t0 + CHUNK, TS) - t0;                    // 32 (31 for last)

    float mem[8], out[8];
    {
        const float4* sb = (const float4*)(g_S + (size_t)c * (Bb * O) + b * O);
        float4 m0 = sb[lane], m1 = sb[32 + lane];
        mem[0] = m0.x; mem[1] = m0.y; mem[2] = m0.z; mem[3] = m0.w;
        mem[4] = m1.x; mem[5] = m1.y; mem[6] = m1.z; mem[7] = m1.w;
    }
#pragma unroll
    for (int j = 0; j < 8; j++) out[j] = 0.f;

    const float4* hb = (const float4*)(g_h2 + ((size_t)b * T + t0) * O);
    for (int i = 0; i < niter; ++i) {
        float4 h0 = hb[i * 64 + lane];
        float4 h1 = hb[i * 64 + 32 + lane];
        float hv[8] = {h0.x, h0.y, h0.z, h0.w, h1.x, h1.y, h1.z, h1.w};
        float e[8];
        float s = 0.f;
#pragma unroll
        for (int j = 0; j < 8; j++) {
            mem[j] = fmaf(ALPHA_F, mem[j], OMA_F * hv[j]);
            e[j] = __expf(mem[j]);     // |mem| small: no max-subtract needed
            s += e[j];
        }
#pragma unroll
        for (int d = 16; d > 0; d >>= 1) s += __shfl_xor_sync(0xffffffffu, s, d);
        float inv = 1.0f / s;
#pragma unroll
        for (int j = 0; j < 8; j++) out[j] = fmaf(e[j], inv, out[j]);
    }

    float4* pb = (float4*)(g_part + (size_t)c * (Bb * O) + b * O);
    pb[lane]      = make_float4(out[0], out[1], out[2], out[3]);
    pb[32 + lane] = make_float4(out[4], out[5], out[6], out[7]);
}

// ---------------- kernel 5: deterministic reduce of chunk partials ----------------
__global__ void k_reduce(float* __restrict__ out) {
    int i = blockIdx.x * blockDim.x + threadIdx.x;   // 0..32767
    float s = 0.f;
#pragma unroll
    for (int c = 0; c < NC; c++) s += g_part[c * (Bb * O) + i];
    out[i] = s;
}

// ---------------- launch ----------------
extern "C" void kernel_launch(void* const* d_in, const int* in_sizes, int n_in,
                              void* d_out, int out_size) {
    const float* x = (const float*)d_in[0];
    const float* w = (const float*)d_in[1];
    float* out = (float*)d_out;

    k_convw<<<(H * O) / 256, 256>>>(w);

    cudaFuncSetAttribute(k_gemm, cudaFuncAttributeMaxDynamicSharedMemorySize, 98304);
    k_gemm<<<M_TOTAL / BM, 512, 98304>>>(x);

    k_carry<<<(Bb * (NC - 1)) / 8, 256>>>();   // 1920 warps
    k_scanS<<<(Bb * O) / 256, 256>>>();
    k_soft<<<(Bb * NC) / 8, 256>>>();          // 2048 warps
    k_reduce<<<(Bb * O) / 256, 256>>>(out);
}

// round 4
// speedup vs baseline: 1.2656x; 1.2656x over previous
#include <cuda_runtime.h>
#include <cuda_bf16.h>
#include <cstdint>

// ---------------- problem constants ----------------
#define Bb 128
#define T 512
#define H 1024
#define O 256
#define TS 511              // scan steps = T-1
#define M_TOTAL (Bb*T)      // 65536
#define CHUNK 32
#define NC 16               // 16*32 = 512 >= 511

#define ALPHA_F   0.9048374180359595f
#define OMA_F     0.09516258196404048f
#define ALPHA32_F 0.040762204f          // alpha^32

// ---------------- scratch (static device arrays; no allocation) ----------------
__device__ __nv_bfloat16  g_h2b[(size_t)M_TOTAL * O];  // 32 MB (bf16 h2)
__device__ __nv_bfloat16  g_wbf[H * O];                // 512 KB
__device__ float          g_L[NC * Bb * O];            // chunk local sums
__device__ float          g_S[NC * Bb * O];            // mem_start per chunk
__device__ float          g_part[NC * Bb * O];         // per-chunk softmax partials

// ---------------- kernel 0: W fp32 -> bf16 ----------------
__global__ void k_convw(const float* __restrict__ w) {
    int i = blockIdx.x * blockDim.x + threadIdx.x;
    if (i < H * O) g_wbf[i] = __float2bfloat16(w[i]);
}

// ---------------- kernel 1: GEMM h2 = x @ W (bf16 mma.sync, 3-stage pipeline)
//                  + fused chunk-carry epilogue ----------------
#define BM 128
#define BK 64
#define NKT (H / BK)        // 16
#define STG 49152           // per-stage smem: A 16KB + B 32KB
#define GSM_BYTES (3*STG + 1024)

__device__ __forceinline__ unsigned a_swz(int m, int kb) {
    unsigned off = (unsigned)(m * 128 + kb);        // 128B rows
    return off ^ ((off >> 3) & 0x70);
}
__device__ __forceinline__ unsigned b_swz(int k, int nb) {
    unsigned off = (unsigned)(k * 512 + nb);        // 512B rows
    return off ^ ((off >> 5) & 0x70);
}

#define CP_ASYNC16(dst, src) \
    asm volatile("cp.async.cg.shared.global [%0], [%1], 16;" :: "r"(dst), "l"(src))
#define CP_COMMIT() asm volatile("cp.async.commit_group;")

__global__ __launch_bounds__(512, 1) void k_gemm(const float* __restrict__ x) {
    extern __shared__ __align__(16) unsigned char smraw[];
    const unsigned base0 = (unsigned)__cvta_generic_to_shared(smraw);
    const unsigned base  = (base0 + 1023u) & ~1023u;

    const int tid  = threadIdx.x;
    const int lane = tid & 31;
    const int wid  = tid >> 5;
    const int wm   = wid >> 2;        // 0..3  (rows of 32)
    const int wn   = wid & 3;         // 0..3  (cols of 64)
    const int row0 = blockIdx.x * BM;

    float acc[2][8][4];
#pragma unroll
    for (int i = 0; i < 2; i++)
#pragma unroll
        for (int j = 0; j < 8; j++)
#pragma unroll
            for (int k = 0; k < 4; k++) acc[i][j][k] = 0.f;

    // ---- helpers to issue loads (indices recomputed to save registers) ----
    float4 av[4];   // A tile fragment in flight (for tile kt+1)

    // B(0)->s0, B(1)->s1
#pragma unroll
    for (int s = 0; s < 2; s++) {
        const unsigned bsb = base + s * STG + 16384u;
#pragma unroll
        for (int i = 0; i < 4; i++) {
            int idx = tid + 512 * i;
            int bk = idx >> 5, bc = idx & 31;
            unsigned dst = bsb + b_swz(bk, bc * 16);
            const __nv_bfloat16* src = g_wbf + (size_t)(s * BK + bk) * O + bc * 8;
            CP_ASYNC16(dst, src);
        }
        CP_COMMIT();
    }

    // A(0) -> regs -> s0
#pragma unroll
    for (int i = 0; i < 4; i++) {
        int idx = tid + 512 * i;
        av[i] = *reinterpret_cast<const float4*>(
            x + (size_t)(row0 + (idx >> 4)) * H + (idx & 15) * 4);
    }
#pragma unroll
    for (int i = 0; i < 4; i++) {
        int idx = tid + 512 * i;
        unsigned dst = base + a_swz(idx >> 4, (idx & 15) * 8);
        __nv_bfloat162 lo = __floats2bfloat162_rn(av[i].x, av[i].y);
        __nv_bfloat162 hi = __floats2bfloat162_rn(av[i].z, av[i].w);
        unsigned ulo = *reinterpret_cast<unsigned*>(&lo);
        unsigned uhi = *reinterpret_cast<unsigned*>(&hi);
        asm volatile("st.shared.v2.b32 [%0], {%1,%2};" :: "r"(dst), "r"(ulo), "r"(uhi));
    }
    // A(1) -> regs (STS'd at top of iter 0)
#pragma unroll
    for (int i = 0; i < 4; i++) {
        int idx = tid + 512 * i;
        av[i] = *reinterpret_cast<const float4*>(
            x + (size_t)(row0 + (idx >> 4)) * H + BK + (idx & 15) * 4);
    }
    asm volatile("cp.async.wait_group 1;");   // B(0) resident
    __syncthreads();

    // ---- main loop ----
    for (int kt = 0; kt < NKT; ++kt) {
        const int cur = kt % 3;
        const unsigned asb = base + cur * STG;
        const unsigned bsb = asb + 16384u;

        // STS A(kt+1) (loaded last iteration) into slot (kt+1)%3
        if (kt + 1 < NKT) {
            const unsigned asn = base + ((kt + 1) % 3) * STG;
#pragma unroll
            for (int i = 0; i < 4; i++) {
                int idx = tid + 512 * i;
                unsigned dst = asn + a_swz(idx >> 4, (idx & 15) * 8);
                __nv_bfloat162 lo = __floats2bfloat162_rn(av[i].x, av[i].y);
                __nv_bfloat162 hi = __floats2bfloat162_rn(av[i].z, av[i].w);
                unsigned ulo = *reinterpret_cast<unsigned*>(&lo);
                unsigned uhi = *reinterpret_cast<unsigned*>(&hi);
                asm volatile("st.shared.v2.b32 [%0], {%1,%2};" :: "r"(dst), "r"(ulo), "r"(uhi));
            }
        }
        // issue B(kt+2) + LDG A(kt+2)
        if (kt + 2 < NKT) {
            const unsigned bsn = base + ((kt + 2) % 3) * STG + 16384u;
#pragma unroll
            for (int i = 0; i < 4; i++) {
                int idx = tid + 512 * i;
                int bk = idx >> 5, bc = idx & 31;
                unsigned dst = bsn + b_swz(bk, bc * 16);
                const __nv_bfloat16* src =
                    g_wbf + (size_t)((kt + 2) * BK + bk) * O + bc * 8;
                CP_ASYNC16(dst, src);
            }
            CP_COMMIT();
#pragma unroll
            for (int i = 0; i < 4; i++) {
                int idx = tid + 512 * i;
                av[i] = *reinterpret_cast<const float4*>(
                    x + (size_t)(row0 + (idx >> 4)) * H + (kt + 2) * BK + (idx & 15) * 4);
            }
        }

        // ---- compute current tile ----
#pragma unroll
        for (int ks = 0; ks < 4; ++ks) {
            const int k0 = ks * 16;
            unsigned af[2][4];
#pragma unroll
            for (int mt = 0; mt < 2; mt++) {
                int q = lane >> 3, r = lane & 7;
                int mrow = wm * 32 + mt * 16 + ((q & 1) << 3) + r;
                int kk = k0 + ((q >> 1) << 3);
                unsigned addr = asb + a_swz(mrow, kk * 2);
                asm volatile("ldmatrix.sync.aligned.m8n8.x4.shared.b16 {%0,%1,%2,%3}, [%4];\n"
                             : "=r"(af[mt][0]), "=r"(af[mt][1]), "=r"(af[mt][2]), "=r"(af[mt][3])
                             : "r"(addr));
            }
            unsigned bf[8][2];
#pragma unroll
            for (int g4 = 0; g4 < 4; g4++) {
                int q = lane >> 3, r = lane & 7;
                int kk = k0 + ((q & 1) << 3) + r;
                int nn = wn * 64 + g4 * 16 + ((q >> 1) << 3);
                unsigned addr = bsb + b_swz(kk, nn * 2);
                asm volatile("ldmatrix.sync.aligned.m8n8.x4.trans.shared.b16 {%0,%1,%2,%3}, [%4];\n"
                             : "=r"(bf[2 * g4][0]), "=r"(bf[2 * g4][1]),
                               "=r"(bf[2 * g4 + 1][0]), "=r"(bf[2 * g4 + 1][1])
                             : "r"(addr));
            }
#pragma unroll
            for (int mt = 0; mt < 2; mt++)
#pragma unroll
                for (int nt = 0; nt < 8; nt++)
                    asm volatile(
                        "mma.sync.aligned.m16n8k16.row.col.f32.bf16.bf16.f32 "
                        "{%0,%1,%2,%3}, {%4,%5,%6,%7}, {%8,%9}, {%0,%1,%2,%3};\n"
                        : "+f"(acc[mt][nt][0]), "+f"(acc[mt][nt][1]),
                          "+f"(acc[mt][nt][2]), "+f"(acc[mt][nt][3])
                        : "r"(af[mt][0]), "r"(af[mt][1]), "r"(af[mt][2]), "r"(af[mt][3]),
                          "r"(bf[nt][0]), "r"(bf[nt][1]));
        }

        if (kt + 2 < NKT) asm volatile("cp.async.wait_group 1;");
        else              asm volatile("cp.async.wait_group 0;");
        __syncthreads();
    }

    // ---- fused epilogue: store h2 (bf16) + chunk-carry L ----
    const int g  = lane >> 2, cc = lane & 3;
    const int bidx = row0 >> 9;                       // batch
    const int cg   = ((row0 & (T - 1)) >> 5) + wm;    // global chunk of this warp
    // coefficients (1-a)*a^(31-r) for this thread's 4 rows r = g, g+8, g+16, g+24
    const float K0 = OMA_F * __expf(-0.1f * (31 - g));
    const float K1 = OMA_F * __expf(-0.1f * (23 - g));
    const float K2 = OMA_F * __expf(-0.1f * (15 - g));
    const float K3 = OMA_F * __expf(-0.1f * (7  - g));

    float Lp[16];
#pragma unroll
    for (int nt = 0; nt < 8; nt++) {
        const int rm  = row0 + wm * 32 + g;
        const int col = wn * 64 + nt * 8 + 2 * cc;
        __nv_bfloat162 s0 = __floats2bfloat162_rn(acc[0][nt][0], acc[0][nt][1]);
        __nv_bfloat162 s1 = __floats2bfloat162_rn(acc[0][nt][2], acc[0][nt][3]);
        __nv_bfloat162 s2 = __floats2bfloat162_rn(acc[1][nt][0], acc[1][nt][1]);
        __nv_bfloat162 s3 = __floats2bfloat162_rn(acc[1][nt][2], acc[1][nt][3]);
        *reinterpret_cast<__nv_bfloat162*>(g_h2b + (size_t)(rm)      * O + col) = s0;
        *reinterpret_cast<__nv_bfloat162*>(g_h2b + (size_t)(rm + 8)  * O + col) = s1;
        *reinterpret_cast<__nv_bfloat162*>(g_h2b + (size_t)(rm + 16) * O + col) = s2;
        *reinterpret_cast<__nv_bfloat162*>(g_h2b + (size_t)(rm + 24) * O + col) = s3;
        Lp[2 * nt]     = K0 * acc[0][nt][0] + K1 * acc[0][nt][2]
                       + K2 * acc[1][nt][0] + K3 * acc[1][nt][2];
        Lp[2 * nt + 1] = K0 * acc[0][nt][1] + K1 * acc[0][nt][3]
                       + K2 * acc[1][nt][1] + K3 * acc[1][nt][3];
    }
#pragma unroll
    for (int j = 0; j < 16; j++) {
        Lp[j] += __shfl_xor_sync(0xffffffffu, Lp[j], 4);
        Lp[j] += __shfl_xor_sync(0xffffffffu, Lp[j], 8);
        Lp[j] += __shfl_xor_sync(0xffffffffu, Lp[j], 16);
    }
    if (lane < 4) {
        float* dst = g_L + ((size_t)cg * Bb + bidx) * O + wn * 64 + 2 * lane;
#pragma unroll
        for (int nt = 0; nt < 8; nt++)
            *reinterpret_cast<float2*>(dst + nt * 8) = make_float2(Lp[2 * nt], Lp[2 * nt + 1]);
    }
}

// ---------------- kernel 2: sequential scan of chunk carries (MLP=15 prefetch) ----------------
__global__ void k_scanS() {
    int i = blockIdx.x * blockDim.x + threadIdx.x;   // 0..32767 == b*256+o
    float v[NC - 1];
#pragma unroll
    for (int c = 0; c < NC - 1; ++c) v[c] = g_L[c * (Bb * O) + i];  // independent loads
    float S = 0.f;
    g_S[i] = 0.f;
#pragma unroll
    for (int c = 0; c < NC - 1; ++c) {
        S = fmaf(ALPHA32_F, S, v[c]);
        g_S[(c + 1) * (Bb * O) + i] = S;
    }
}

// ---------------- kernel 3: per-chunk softmax scan (exact, bf16 h2) ----------------
__global__ void k_soft() {
    int w = (blockIdx.x * blockDim.x + threadIdx.x) >> 5;   // 0..2047
    int lane = threadIdx.x & 31;
    int b = w & 127;
    int c = w >> 7;                                          // 0..15
    int t0 = c * CHUNK;
    int niter = min(t0 + CHUNK, TS) - t0;                    // 32 (31 for last)

    float mem[8], out[8];
    {
        const float4* sb = (const float4*)(g_S + (size_t)c * (Bb * O) + b * O);
        float4 m0 = sb[2 * lane], m1 = sb[2 * lane + 1];     // cols lane*8..+7
        mem[0] = m0.x; mem[1] = m0.y; mem[2] = m0.z; mem[3] = m0.w;
        mem[4] = m1.x; mem[5] = m1.y; mem[6] = m1.z; mem[7] = m1.w;
    }
#pragma unroll
    for (int j = 0; j < 8; j++) out[j] = 0.f;

    const uint4* hb = (const uint4*)(g_h2b + ((size_t)b * T + t0) * O);
    for (int i = 0; i < niter; ++i) {
        uint4 hv = hb[i * 32 + lane];                        // 8 bf16 (cols lane*8..+7)
        float2 f0 = __bfloat1622float2(*reinterpret_cast<__nv_bfloat162*>(&hv.x));
        float2 f1 = __bfloat1622float2(*reinterpret_cast<__nv_bfloat162*>(&hv.y));
        float2 f2 = __bfloat1622float2(*reinterpret_cast<__nv_bfloat162*>(&hv.z));
        float2 f3 = __bfloat1622float2(*reinterpret_cast<__nv_bfloat162*>(&hv.w));
        float hvv[8] = {f0.x, f0.y, f1.x, f1.y, f2.x, f2.y, f3.x, f3.y};
        float e[8];
        float s = 0.f;
#pragma unroll
        for (int j = 0; j < 8; j++) {
            mem[j] = fmaf(ALPHA_F, mem[j], OMA_F * hvv[j]);
            e[j] = __expf(mem[j]);     // |mem| small: no max-subtract needed
            s += e[j];
        }
#pragma unroll
        for (int d = 16; d > 0; d >>= 1) s += __shfl_xor_sync(0xffffffffu, s, d);
        float inv = 1.0f / s;
#pragma unroll
        for (int j = 0; j < 8; j++) out[j] = fmaf(e[j], inv, out[j]);
    }

    float4* pb = (float4*)(g_part + (size_t)c * (Bb * O) + b * O);
    pb[2 * lane]     = make_float4(out[0], out[1], out[2], out[3]);
    pb[2 * lane + 1] = make_float4(out[4], out[5], out[6], out[7]);
}

// ---------------- kernel 4: deterministic reduce of chunk partials ----------------
__global__ void k_reduce(float* __restrict__ out) {
    int i = blockIdx.x * blockDim.x + threadIdx.x;   // 0..32767
    float s = 0.f;
#pragma unroll
    for (int c = 0; c < NC; c++) s += g_part[c * (Bb * O) + i];
    out[i] = s;
}

// ---------------- launch ----------------
extern "C" void kernel_launch(void* const* d_in, const int* in_sizes, int n_in,
                              void* d_out, int out_size) {
    const float* x = (const float*)d_in[0];
    const float* w = (const float*)d_in[1];
    float* out = (float*)d_out;

    k_convw<<<(H * O) / 256, 256>>>(w);

    cudaFuncSetAttribute(k_gemm, cudaFuncAttributeMaxDynamicSharedMemorySize, GSM_BYTES);
    k_gemm<<<M_TOTAL / BM, 512, GSM_BYTES>>>(x);

    k_scanS<<<(Bb * O) / 256, 256>>>();
    k_soft<<<(Bb * NC) / 8, 256>>>();          // 2048 warps
    k_reduce<<<(Bb * O) / 256, 256>>>(out);
}

// round 6
// speedup vs baseline: 1.5178x; 1.1992x over previous
#include <cuda_runtime.h>
#include <cuda_bf16.h>
#include <cstdint>

// ---------------- problem constants ----------------
#define Bb 128
#define T 512
#define H 1024
#define O 256
#define TS 511              // scan steps = T-1
#define M_TOTAL (Bb*T)      // 65536
#define CHUNK 16
#define NC 32               // 32*16 = 512 >= 511

#define ALPHA_F   0.9048374180359595f
#define OMA_F     0.09516258196404048f
#define ALPHA16_F 0.2018965180f         // alpha^16 = exp(-1.6)

// ---------------- scratch (static device arrays; no allocation) ----------------
__device__ __nv_bfloat16  g_h2b[(size_t)M_TOTAL * O];  // 32 MB (bf16 h2)
__device__ __nv_bfloat16  g_wbf[H * O];                // 512 KB
__device__ float          g_L[NC * Bb * O];            // chunk local sums   (4 MB)
__device__ float          g_S[NC * Bb * O];            // mem_start per chunk(4 MB)
__device__ float          g_part[NC * Bb * O];         // softmax partials   (4 MB)

// ---------------- kernel 0: W fp32 -> bf16 ----------------
__global__ void k_convw(const float* __restrict__ w) {
    int i = blockIdx.x * blockDim.x + threadIdx.x;
    if (i < H * O) g_wbf[i] = __float2bfloat16(w[i]);
}

// ---------------- kernel 1: GEMM h2 = x @ W (bf16 mma.sync, 2-stage, 2 CTA/SM)
//                  + fused chunk-carry epilogue ----------------
#define BM 64
#define BK 64
#define NKT (H / BK)        // 16
#define STG 40960           // per-stage smem: A 8KB + B 32KB
#define GSM_BYTES (2*STG + 1024)

__device__ __forceinline__ unsigned a_swz(int m, int kb) {
    unsigned off = (unsigned)(m * 128 + kb);        // 128B rows
    return off ^ ((off >> 3) & 0x70);
}
__device__ __forceinline__ unsigned b_swz(int k, int nb) {
    unsigned off = (unsigned)(k * 512 + nb);        // 512B rows
    return off ^ ((off >> 5) & 0x70);
}

#define CP_ASYNC16(dst, src) \
    asm volatile("cp.async.cg.shared.global [%0], [%1], 16;" :: "r"(dst), "l"(src))
#define CP_COMMIT() asm volatile("cp.async.commit_group;")

__global__ __launch_bounds__(256, 2) void k_gemm(const float* __restrict__ x) {
    extern __shared__ __align__(16) unsigned char smraw[];
    const unsigned base0 = (unsigned)__cvta_generic_to_shared(smraw);
    const unsigned base  = (base0 + 1023u) & ~1023u;

    const int tid  = threadIdx.x;
    const int lane = tid & 31;
    const int wid  = tid >> 5;
    const int wm   = wid >> 2;        // 0..1  (rows of 32)
    const int wn   = wid & 3;         // 0..3  (cols of 64)
    const int row0 = blockIdx.x * BM;

    float acc[2][8][4];
#pragma unroll
    for (int i = 0; i < 2; i++)
#pragma unroll
        for (int j = 0; j < 8; j++)
#pragma unroll
            for (int k = 0; k < 4; k++) acc[i][j][k] = 0.f;

    float4 av[4];   // A fragment in flight (tile kt+1)

    // ---- prologue ----
    // B(0) -> stage 0
#pragma unroll
    for (int i = 0; i < 8; i++) {
        int idx = tid + 256 * i;
        int bk = idx >> 5, bc = idx & 31;
        unsigned dst = base + 8192u + b_swz(bk, bc * 16);
        CP_ASYNC16(dst, g_wbf + (size_t)bk * O + bc * 8);
    }
    CP_COMMIT();
    // A(0) -> regs -> stage 0
#pragma unroll
    for (int i = 0; i < 4; i++) {
        int idx = tid + 256 * i;
        av[i] = *reinterpret_cast<const float4*>(
            x + (size_t)(row0 + (idx >> 4)) * H + (idx & 15) * 4);
    }
#pragma unroll
    for (int i = 0; i < 4; i++) {
        int idx = tid + 256 * i;
        unsigned dst = base + a_swz(idx >> 4, (idx & 15) * 8);
        __nv_bfloat162 lo = __floats2bfloat162_rn(av[i].x, av[i].y);
        __nv_bfloat162 hi = __floats2bfloat162_rn(av[i].z, av[i].w);
        unsigned ulo = *reinterpret_cast<unsigned*>(&lo);
        unsigned uhi = *reinterpret_cast<unsigned*>(&hi);
        asm volatile("st.shared.v2.b32 [%0], {%1,%2};" :: "r"(dst), "r"(ulo), "r"(uhi));
    }
    // A(1) -> regs
#pragma unroll
    for (int i = 0; i < 4; i++) {
        int idx = tid + 256 * i;
        av[i] = *reinterpret_cast<const float4*>(
            x + (size_t)(row0 + (idx >> 4)) * H + BK + (idx & 15) * 4);
    }
    asm volatile("cp.async.wait_group 0;");
    __syncthreads();

    // ---- main loop (2-stage) ----
    for (int kt = 0; kt < NKT; ++kt) {
        const unsigned asb = base + (kt & 1) * STG;
        const unsigned bsb = asb + 8192u;

        if (kt + 1 < NKT) {
            const unsigned asn = base + ((kt + 1) & 1) * STG;
            // STS A(kt+1) from regs
#pragma unroll
            for (int i = 0; i < 4; i++) {
                int idx = tid + 256 * i;
                unsigned dst = asn + a_swz(idx >> 4, (idx & 15) * 8);
                __nv_bfloat162 lo = __floats2bfloat162_rn(av[i].x, av[i].y);
                __nv_bfloat162 hi = __floats2bfloat162_rn(av[i].z, av[i].w);
                unsigned ulo = *reinterpret_cast<unsigned*>(&lo);
                unsigned uhi = *reinterpret_cast<unsigned*>(&hi);
                asm volatile("st.shared.v2.b32 [%0], {%1,%2};" :: "r"(dst), "r"(ulo), "r"(uhi));
            }
            // cp.async B(kt+1)
            const unsigned bsn = asn + 8192u;
#pragma unroll
            for (int i = 0; i < 8; i++) {
                int idx = tid + 256 * i;
                int bk = idx >> 5, bc = idx & 31;
                unsigned dst = bsn + b_swz(bk, bc * 16);
                CP_ASYNC16(dst, g_wbf + (size_t)((kt + 1) * BK + bk) * O + bc * 8);
            }
            CP_COMMIT();
            // LDG A(kt+2)
            if (kt + 2 < NKT) {
#pragma unroll
                for (int i = 0; i < 4; i++) {
                    int idx = tid + 256 * i;
                    av[i] = *reinterpret_cast<const float4*>(
                        x + (size_t)(row0 + (idx >> 4)) * H + (kt + 2) * BK + (idx & 15) * 4);
                }
            }
        }

        // ---- compute current tile ----
#pragma unroll
        for (int ks = 0; ks < 4; ++ks) {
            const int k0 = ks * 16;
            unsigned af[2][4];
#pragma unroll
            for (int mt = 0; mt < 2; mt++) {
                int q = lane >> 3, r = lane & 7;
                int mrow = wm * 32 + mt * 16 + ((q & 1) << 3) + r;
                int kk = k0 + ((q >> 1) << 3);
                unsigned addr = asb + a_swz(mrow, kk * 2);
                asm volatile("ldmatrix.sync.aligned.m8n8.x4.shared.b16 {%0,%1,%2,%3}, [%4];\n"
                             : "=r"(af[mt][0]), "=r"(af[mt][1]), "=r"(af[mt][2]), "=r"(af[mt][3])
                             : "r"(addr));
            }
            unsigned bf[8][2];
#pragma unroll
            for (int g4 = 0; g4 < 4; g4++) {
                int q = lane >> 3, r = lane & 7;
                int kk = k0 + ((q & 1) << 3) + r;
                int nn = wn * 64 + g4 * 16 + ((q >> 1) << 3);
                unsigned addr = bsb + b_swz(kk, nn * 2);
                asm volatile("ldmatrix.sync.aligned.m8n8.x4.trans.shared.b16 {%0,%1,%2,%3}, [%4];\n"
                             : "=r"(bf[2 * g4][0]), "=r"(bf[2 * g4][1]),
                               "=r"(bf[2 * g4 + 1][0]), "=r"(bf[2 * g4 + 1][1])
                             : "r"(addr));
            }
#pragma unroll
            for (int mt = 0; mt < 2; mt++)
#pragma unroll
                for (int nt = 0; nt < 8; nt++)
                    asm volatile(
                        "mma.sync.aligned.m16n8k16.row.col.f32.bf16.bf16.f32 "
                        "{%0,%1,%2,%3}, {%4,%5,%6,%7}, {%8,%9}, {%0,%1,%2,%3};\n"
                        : "+f"(acc[mt][nt][0]), "+f"(acc[mt][nt][1]),
                          "+f"(acc[mt][nt][2]), "+f"(acc[mt][nt][3])
                        : "r"(af[mt][0]), "r"(af[mt][1]), "r"(af[mt][2]), "r"(af[mt][3]),
                          "r"(bf[nt][0]), "r"(bf[nt][1]));
        }

        if (kt + 1 < NKT) {
            asm volatile("cp.async.wait_group 0;");
            __syncthreads();
        }
    }

    // ---- fused epilogue: store h2 (bf16) + per-16-chunk carries ----
    const int g    = lane >> 2;
    const int bidx = row0 >> 9;                          // batch
    const int c0   = ((row0 & (T - 1)) >> 4) + 2 * wm;   // chunk of acc[0] rows
    // coeffs (1-a)*a^(15-r) for local rows r = g (vals 0,1) and r = g+8 (vals 2,3)
    const float KA = OMA_F * __expf(-0.1f * (15 - g));
    const float KB = OMA_F * __expf(-0.1f * (7  - g));

    float LA[16], LB[16];
#pragma unroll
    for (int nt = 0; nt < 8; nt++) {
        const int cc  = lane & 3;
        const int rm  = row0 + wm * 32 + g;
        const int col = wn * 64 + nt * 8 + 2 * cc;
        __nv_bfloat162 s0 = __floats2bfloat162_rn(acc[0][nt][0], acc[0][nt][1]);
        __nv_bfloat162 s1 = __floats2bfloat162_rn(acc[0][nt][2], acc[0][nt][3]);
        __nv_bfloat162 s2 = __floats2bfloat162_rn(acc[1][nt][0], acc[1][nt][1]);
        __nv_bfloat162 s3 = __floats2bfloat162_rn(acc[1][nt][2], acc[1][nt][3]);
        *reinterpret_cast<__nv_bfloat162*>(g_h2b + (size_t)(rm)      * O + col) = s0;
        *reinterpret_cast<__nv_bfloat162*>(g_h2b + (size_t)(rm + 8)  * O + col) = s1;
        *reinterpret_cast<__nv_bfloat162*>(g_h2b + (size_t)(rm + 16) * O + col) = s2;
        *reinterpret_cast<__nv_bfloat162*>(g_h2b + (size_t)(rm + 24) * O + col) = s3;
        LA[2 * nt]     = KA * acc[0][nt][0] + KB * acc[0][nt][2];
        LA[2 * nt + 1] = KA * acc[0][nt][1] + KB * acc[0][nt][3];
        LB[2 * nt]     = KA * acc[1][nt][0] + KB * acc[1][nt][2];
        LB[2 * nt + 1] = KA * acc[1][nt][1] + KB * acc[1][nt][3];
    }
#pragma unroll
    for (int j = 0; j < 16; j++) {
        LA[j] += __shfl_xor_sync(0xffffffffu, LA[j], 4);
        LA[j] += __shfl_xor_sync(0xffffffffu, LA[j], 8);
        LA[j] += __shfl_xor_sync(0xffffffffu, LA[j], 16);
        LB[j] += __shfl_xor_sync(0xffffffffu, LB[j], 4);
        LB[j] += __shfl_xor_sync(0xffffffffu, LB[j], 8);
        LB[j] += __shfl_xor_sync(0xffffffffu, LB[j], 16);
    }
    if (lane < 4) {
        float* dA = g_L + ((size_t)c0 * Bb + bidx) * O + wn * 64 + 2 * lane;
        float* dB = g_L + ((size_t)(c0 + 1) * Bb + bidx) * O + wn * 64 + 2 * lane;
#pragma unroll
        for (int nt = 0; nt < 8; nt++) {
            *reinterpret_cast<float2*>(dA + nt * 8) = make_float2(LA[2 * nt], LA[2 * nt + 1]);
            *reinterpret_cast<float2*>(dB + nt * 8) = make_float2(LB[2 * nt], LB[2 * nt + 1]);
        }
    }
}

// ---------------- kernel 2: sequential scan of chunk carries (full prefetch) ----------------
__global__ void k_scanS() {
    int i = blockIdx.x * blockDim.x + threadIdx.x;   // 0..32767 == b*256+o
    float v[NC - 1];
#pragma unroll
    for (int c = 0; c < NC - 1; ++c) v[c] = g_L[c * (Bb * O) + i];  // independent loads
    float S = 0.f;
    g_S[i] = 0.f;
#pragma unroll
    for (int c = 0; c < NC - 1; ++c) {
        S = fmaf(ALPHA16_F, S, v[c]);
        g_S[(c + 1) * (Bb * O) + i] = S;
    }
}

// ---------------- kernel 3: per-chunk softmax scan (exact, bf16 h2) ----------------
__global__ void k_soft() {
    int w = (blockIdx.x * blockDim.x + threadIdx.x) >> 5;   // 0..4095
    int lane = threadIdx.x & 31;
    int b = w & 127;
    int c = w >> 7;                                          // 0..31
    int t0 = c * CHUNK;
    int niter = min(t0 + CHUNK, TS) - t0;                    // 16 (15 for last)

    float mem[8], out[8];
    {
        const float4* sb = (const float4*)(g_S + (size_t)c * (Bb * O) + b * O);
        float4 m0 = sb[2 * lane], m1 = sb[2 * lane + 1];     // cols lane*8..+7
        mem[0] = m0.x; mem[1] = m0.y; mem[2] = m0.z; mem[3] = m0.w;
        mem[4] = m1.x; mem[5] = m1.y; mem[6] = m1.z; mem[7] = m1.w;
    }
#pragma unroll
    for (int j = 0; j < 8; j++) out[j] = 0.f;

    const uint4* hb = (const uint4*)(g_h2b + ((size_t)b * T + t0) * O);
    uint4 hv = hb[lane];                                     // prefetch i=0
    for (int i = 0; i < niter; ++i) {
        uint4 nx = make_uint4(0, 0, 0, 0);
        if (i + 1 < niter) nx = hb[(i + 1) * 32 + lane];     // prefetch next
        float2 f0 = __bfloat1622float2(*reinterpret_cast<__nv_bfloat162*>(&hv.x));
        float2 f1 = __bfloat1622float2(*reinterpret_cast<__nv_bfloat162*>(&hv.y));
        float2 f2 = __bfloat1622float2(*reinterpret_cast<__nv_bfloat162*>(&hv.z));
        float2 f3 = __bfloat1622float2(*reinterpret_cast<__nv_bfloat162*>(&hv.w));
        float hvv[8] = {f0.x, f0.y, f1.x, f1.y, f2.x, f2.y, f3.x, f3.y};
        float e[8];
        float s = 0.f;
#pragma unroll
        for (int j = 0; j < 8; j++) {
            mem[j] = fmaf(ALPHA_F, mem[j], OMA_F * hvv[j]);
            e[j] = __expf(mem[j]);     // |mem| small: no max-subtract needed
            s += e[j];
        }
#pragma unroll
        for (int d = 16; d > 0; d >>= 1) s += __shfl_xor_sync(0xffffffffu, s, d);
        float inv = 1.0f / s;
#pragma unroll
        for (int j = 0; j < 8; j++) out[j] = fmaf(e[j], inv, out[j]);
        hv = nx;
    }

    float4* pb = (float4*)(g_part + (size_t)c * (Bb * O) + b * O);
    pb[2 * lane]     = make_float4(out[0], out[1], out[2], out[3]);
    pb[2 * lane + 1] = make_float4(out[4], out[5], out[6], out[7]);
}

// ---------------- kernel 4: deterministic reduce of chunk partials ----------------
__global__ void k_reduce(float* __restrict__ out) {
    int i = blockIdx.x * blockDim.x + threadIdx.x;   // 0..8191 (float4 units)
    const float4* p = (const float4*)g_part;
    float4 s = make_float4(0.f, 0.f, 0.f, 0.f);
#pragma unroll
    for (int c = 0; c < NC; c++) {
        float4 v = p[c * (Bb * O / 4) + i];
        s.x += v.x; s.y += v.y; s.z += v.z; s.w += v.w;
    }
    reinterpret_cast<float4*>(out)[i] = s;
}

// ---------------- launch ----------------
extern "C" void kernel_launch(void* const* d_in, const int* in_sizes, int n_in,
                              void* d_out, int out_size) {
    const float* x = (const float*)d_in[0];
    const float* w = (const float*)d_in[1];
    float* out = (float*)d_out;

    k_convw<<<(H * O) / 256, 256>>>(w);

    cudaFuncSetAttribute(k_gemm, cudaFuncAttributeMaxDynamicSharedMemorySize, GSM_BYTES);
    k_gemm<<<M_TOTAL / BM, 256, GSM_BYTES>>>(x);

    k_scanS<<<(Bb * O) / 256, 256>>>();
    k_soft<<<(Bb * NC) / 8, 256>>>();          // 4096 warps
    k_reduce<<<(Bb * O / 4) / 256, 256>>>(out);
}